// round 3
// baseline (speedup 1.0000x reference)
#include <cuda_runtime.h>

#define M_NODES   8192
#define K_PAR     8
#define C_CFG     256
#define N_LAYERS  8
#define NBLOCKS   256
#define NTHREADS  256

__device__ __forceinline__ float fast_sigmoid(float x) {
    float t = -1.4426950408889634f * x;
    float e;
    asm("ex2.approx.f32 %0, %1;" : "=f"(e) : "f"(t));
    float d = 1.0f + e;
    float r;
    asm("rcp.approx.f32 %0, %1;" : "=f"(r) : "f"(d));
    return r;
}

// Sense-reversing grid barrier. State is balanced at the end of every launch
// (count back to 0, gen monotonically increasing), so it is replay-safe.
__device__ unsigned int g_count = 0;
__device__ unsigned int g_gen   = 0;

__device__ __forceinline__ void grid_barrier() {
    __syncthreads();
    __threadfence();                       // release this block's writes
    if (threadIdx.x == 0) {
        unsigned gen = *(volatile unsigned int*)&g_gen;
        unsigned t   = atomicAdd(&g_count, 1u);
        if (t == NBLOCKS - 1) {
            g_count = 0;
            __threadfence();
            atomicAdd(&g_gen, 1u);         // release all spinners
        } else {
            while (*(volatile unsigned int*)&g_gen == gen) { }
        }
    }
    __syncthreads();
    __threadfence();                       // acquire side
}

// 8 lanes per node, 4 nodes per warp (validated fold mapping from R2):
//   config c = i*32 + gl*4 + t ; bit b of c <-> parent (7-b)
//   t bits 0-1 -> parents 7,6 (in-float4 folds)
//   gl bits 2-4 -> parents 5,4,3 (3x shfl_xor)
//   i  bits 5-7 -> parents 2,1,0 (register folds)
__global__ void __launch_bounds__(NTHREADS, 2)
fused_kernel(const float* __restrict__ root,
             const float* __restrict__ cpt,      // [L, M, C]
             const int*   __restrict__ parents,  // [L, M, K]
             float*       __restrict__ out)      // [(L+1)*M]
{
    const int tid   = blockIdx.x * NTHREADS + threadIdx.x;
    const int warp  = tid >> 5;                 // 0..2047
    const int lane  = threadIdx.x & 31;
    const int gl    = lane & 7;
    const int node  = warp * 4 + (lane >> 3);   // 0..8191
    const int pbase = lane & 24;

    // Hoist ALL parent indices (independent of everything).
    int par[N_LAYERS];
#pragma unroll
    for (int l = 0; l < N_LAYERS; l++)
        par[l] = parents[(size_t)l * M_NODES * K_PAR + warp * 32 + lane];

    // Root marginals (tid < M covers all 8192 roots).
    if (tid < M_NODES) out[tid] = fast_sigmoid(root[tid]);

    // Prefetch layer-0 CPT (independent of root barrier).
    float4 va[8], vb[8];
    {
        const float4* b0 = reinterpret_cast<const float4*>(
            cpt + (size_t)node * C_CFG + gl * 4);
#pragma unroll
        for (int i = 0; i < 8; i++) va[i] = b0[i * 8];
    }

    grid_barrier();   // root marginals visible

#pragma unroll
    for (int l = 0; l < N_LAYERS; l++) {
        float4* v = (l & 1) ? vb : va;
        float4* w = (l & 1) ? va : vb;

        // Dependent gather: issue ASAP after barrier.
        float pp = out[(size_t)l * M_NODES + par[l]];

        // Sigmoids overlap the gather latency (independent of pp).
        float s[32];
#pragma unroll
        for (int i = 0; i < 8; i++) {
            s[4*i+0] = fast_sigmoid(v[i].x);
            s[4*i+1] = fast_sigmoid(v[i].y);
            s[4*i+2] = fast_sigmoid(v[i].z);
            s[4*i+3] = fast_sigmoid(v[i].w);
        }

        // Prefetch next layer's CPT BEFORE folds/barrier (overlaps everything).
        if (l + 1 < N_LAYERS) {
            const float4* bn = reinterpret_cast<const float4*>(
                cpt + (size_t)(l + 1) * M_NODES * C_CFG
                    + (size_t)node * C_CFG + gl * 4);
#pragma unroll
            for (int i = 0; i < 8; i++) w[i] = bn[i * 8];
        }

        // Broadcast the 8 parent marginals within the 8-lane group.
        float p[8];
#pragma unroll
        for (int j = 0; j < 8; j++)
            p[j] = __shfl_sync(0xffffffffu, pp, pbase | j);

        // In-register folds: parents 7,6 then 2,1,0.
        float r_i[8];
#pragma unroll
        for (int i = 0; i < 8; i++) {
            float t0 = fmaf(p[7], s[4*i+1] - s[4*i+0], s[4*i+0]);
            float t1 = fmaf(p[7], s[4*i+3] - s[4*i+2], s[4*i+2]);
            r_i[i]   = fmaf(p[6], t1 - t0, t0);
        }
        float q0 = fmaf(p[2], r_i[1] - r_i[0], r_i[0]);
        float q1 = fmaf(p[2], r_i[3] - r_i[2], r_i[2]);
        float q2 = fmaf(p[2], r_i[5] - r_i[4], r_i[4]);
        float q3 = fmaf(p[2], r_i[7] - r_i[6], r_i[6]);
        float h0 = fmaf(p[1], q1 - q0, q0);
        float h1 = fmaf(p[1], q3 - q2, q2);
        float r  = fmaf(p[0], h1 - h0, h0);

        // Cross-lane folds: gl bit b -> parent 5-b.
#pragma unroll
        for (int b = 0; b < 3; b++) {
            int   msk = 1 << b;
            float o   = __shfl_xor_sync(0xffffffffu, r, msk);
            float v0  = (lane & msk) ? o : r;
            float v1  = (lane & msk) ? r : o;
            r = fmaf(p[5 - b], v1 - v0, v0);
        }

        if (gl == 0) out[(size_t)(l + 1) * M_NODES + node] = r;

        grid_barrier();   // layer l+1 marginals visible to all blocks
    }
}

extern "C" void kernel_launch(void* const* d_in, const int* in_sizes, int n_in,
                              void* d_out, int out_size) {
    const float* root    = (const float*)d_in[0];
    const float* cpt     = (const float*)d_in[1];
    const int*   parents = (const int*)  d_in[2];
    float*       out     = (float*)d_out;

    fused_kernel<<<NBLOCKS, NTHREADS>>>(root, cpt, parents, out);
}

// round 4
// speedup vs baseline: 1.2807x; 1.2807x over previous
#include <cuda_runtime.h>

#define M_NODES   8192
#define K_PAR     8
#define C_CFG     256
#define N_LAYERS  8

__device__ __forceinline__ float fast_sigmoid(float x) {
    // sigmoid(x) = 1 / (1 + exp2(-x*log2e))
    float t = -1.4426950408889634f * x;
    float e;
    asm("ex2.approx.f32 %0, %1;" : "=f"(e) : "f"(t));
    float d = 1.0f + e;
    float r;
    asm("rcp.approx.f32 %0, %1;" : "=f"(r) : "f"(d));
    return r;
}

__global__ void root_kernel(const float* __restrict__ root_logits,
                            float* __restrict__ out) {
    int i = blockIdx.x * blockDim.x + threadIdx.x;
    if (i < M_NODES) out[i] = fast_sigmoid(root_logits[i]);
}

// 8 lanes per node, 4 nodes per warp, 4 warps per block (128 thr) -> 512 blocks.
// Lane (gl = lane&7) iteration i holds configs c = i*32 + gl*4 + t.
// Config bit b <-> parent (7-b)  [MSB-first]:
//   t bits 0-1  -> parents 7,6 : in-float4 register folds
//   gl bits 2-4 -> parents 5,4,3: 3x shfl_xor within 8-lane group
//   i bits 5-7  -> parents 2,1,0: register folds across iterations
__global__ void __launch_bounds__(128)
layer_kernel(const float* __restrict__ cpt,     // [M, C]
             const int*   __restrict__ parents, // [M, K]
             const float* __restrict__ prev,    // [M]
             float*       __restrict__ out)     // [M]
{
    const int warp  = (blockIdx.x * 128 + threadIdx.x) >> 5;  // 0..2047
    const int lane  = threadIdx.x & 31;
    const int gl    = lane & 7;
    const int node  = warp * 4 + (lane >> 3);                 // 0..8191
    const int pbase = lane & 24;

    // Independent index load first.
    const int pidx = parents[warp * 32 + lane];

    // Front-batch all 8 CPT LDG.128 (independent; MLP=8).
    const float4* base = reinterpret_cast<const float4*>(
        cpt + (size_t)node * C_CFG + gl * 4);
    float4 v0 = base[0];
    float4 v1 = base[8];
    float4 v2 = base[16];
    float4 v3 = base[24];
    float4 v4 = base[32];
    float4 v5 = base[40];
    float4 v6 = base[48];
    float4 v7 = base[56];

    // Dependent gather issued before the sigmoid burst so MUFU work hides it.
    const float pp = prev[pidx];

    // Sigmoid + fold parents 7,6 per float4 (keeps live registers small).
    float r_i[8];
    {
        float4 vv[8] = {v0, v1, v2, v3, v4, v5, v6, v7};
#pragma unroll
        for (int i = 0; i < 8; i++) {
            float s0 = fast_sigmoid(vv[i].x);
            float s1 = fast_sigmoid(vv[i].y);
            float s2 = fast_sigmoid(vv[i].z);
            float s3 = fast_sigmoid(vv[i].w);
            float t0 = fmaf(pp, 0.0f, 0.0f);   // placeholder prevented; see below
            (void)t0;
            r_i[i] = 0.0f;                      // overwritten after p[] ready
            // store sigmoids packed back into vv for the fold after broadcast
            vv[i].x = s0; vv[i].y = s1; vv[i].z = s2; vv[i].w = s3;
        }

        // Broadcast the 8 parent marginals within the 8-lane group.
        float p[8];
#pragma unroll
        for (int j = 0; j < 8; j++)
            p[j] = __shfl_sync(0xffffffffu, pp, pbase | j);

        // Folds: parents 7,6 per float4.
#pragma unroll
        for (int i = 0; i < 8; i++) {
            float t0 = fmaf(p[7], vv[i].y - vv[i].x, vv[i].x);
            float t1 = fmaf(p[7], vv[i].w - vv[i].z, vv[i].z);
            r_i[i]   = fmaf(p[6], t1 - t0, t0);
        }

        // Folds across iterations: parents 2,1,0.
        float q0 = fmaf(p[2], r_i[1] - r_i[0], r_i[0]);
        float q1 = fmaf(p[2], r_i[3] - r_i[2], r_i[2]);
        float q2 = fmaf(p[2], r_i[5] - r_i[4], r_i[4]);
        float q3 = fmaf(p[2], r_i[7] - r_i[6], r_i[6]);
        float h0 = fmaf(p[1], q1 - q0, q0);
        float h1 = fmaf(p[1], q3 - q2, q2);
        float r  = fmaf(p[0], h1 - h0, h0);

        // Cross-lane folds: gl bit b -> parent 5-b.
#pragma unroll
        for (int b = 0; b < 3; b++) {
            int   msk = 1 << b;
            float o   = __shfl_xor_sync(0xffffffffu, r, msk);
            float a0  = (lane & msk) ? o : r;
            float a1  = (lane & msk) ? r : o;
            r = fmaf(p[5 - b], a1 - a0, a0);
        }

        if (gl == 0) out[node] = r;
    }
}

extern "C" void kernel_launch(void* const* d_in, const int* in_sizes, int n_in,
                              void* d_out, int out_size) {
    const float* root    = (const float*)d_in[0];  // [M]
    const float* cpt     = (const float*)d_in[1];  // [L, M, C]
    const int*   parents = (const int*)  d_in[2];  // [L, M, K]
    float*       out     = (float*)d_out;          // [(L+1)*M]

    root_kernel<<<(M_NODES + 255) / 256, 256>>>(root, out);

    // 16 nodes per 128-thread block -> 512 blocks per layer.
    for (int l = 0; l < N_LAYERS; l++) {
        layer_kernel<<<M_NODES / 16, 128>>>(
            cpt     + (size_t)l * M_NODES * C_CFG,
            parents + (size_t)l * M_NODES * K_PAR,
            out     + (size_t)l * M_NODES,
            out     + (size_t)(l + 1) * M_NODES);
    }
}

// round 5
// speedup vs baseline: 1.3790x; 1.0767x over previous
#include <cuda_runtime.h>
#include <cstdint>

#define M_NODES   8192
#define K_PAR     8
#define C_CFG     256
#define N_LAYERS  8
#define TPB       128
#define NPB       16                          // nodes per block
#define TILE_B    (NPB * C_CFG * 4)           // 16384 bytes

__device__ __forceinline__ uint32_t smem_u32(const void* p) {
    uint32_t a;
    asm("{ .reg .u64 t; cvta.to.shared.u64 t, %1; cvt.u32.u64 %0, t; }"
        : "=r"(a) : "l"(p));
    return a;
}

__device__ __forceinline__ float fast_tanh(float x) {
    float r;
    asm("tanh.approx.f32 %0, %1;" : "=f"(r) : "f"(x));
    return r;
}

__device__ __forceinline__ float acc_sigmoid(float x) {
    float t = -1.4426950408889634f * x, e, r;
    asm("ex2.approx.f32 %0, %1;" : "=f"(e) : "f"(t));
    float d = 1.0f + e;
    asm("rcp.approx.f32 %0, %1;" : "=f"(r) : "f"(d));
    return r;
}

__global__ void root_kernel(const float* __restrict__ root_logits,
                            float* __restrict__ out) {
    int i = blockIdx.x * blockDim.x + threadIdx.x;
    if (i < M_NODES) out[i] = acc_sigmoid(root_logits[i]);
}

// Block: 128 threads / 4 warps, 16 nodes. CPT tile (16 KB, contiguous in gmem)
// arrives via one cp.async.bulk. Fold mapping (validated R2-R4):
//   config c = i*32 + gl*4 + t ; config bit b <-> parent (7-b)
//   t bits 0-1  -> parents 7,6 (register folds)
//   gl bits 2-4 -> parents 5,4,3 (3x shfl_xor)
//   i bits 5-7  -> parents 2,1,0 (register folds)
// We fold tanh values (t = 2*sigma-1); since every fold is a convex combo and
// sum_c w_c = 1, final marginal = 0.5 + 0.5 * folded_tanh.
__global__ void __launch_bounds__(TPB)
layer_kernel(const float* __restrict__ cpt,     // [M, C]
             const int*   __restrict__ parents, // [M, K]
             const float* __restrict__ prev,    // [M]
             float*       __restrict__ out)     // [M]
{
    __shared__ __align__(16) float tile[NPB * C_CFG];
    __shared__ __align__(8)  uint64_t mbar;

    const int tid    = threadIdx.x;
    const int lane   = tid & 31;
    const int wid    = tid >> 5;
    const int gl     = lane & 7;
    const int nlocal = wid * 4 + (lane >> 3);
    const int gwarp  = blockIdx.x * 4 + wid;
    const int pbase  = lane & 24;

    const uint32_t mbar_a = smem_u32(&mbar);
    if (tid == 0) {
        asm volatile("mbarrier.init.shared.b64 [%0], 1;" :: "r"(mbar_a) : "memory");
        asm volatile("fence.proxy.async.shared::cta;" ::: "memory");
    }
    __syncthreads();
    if (tid == 0) {
        asm volatile("mbarrier.arrive.expect_tx.shared.b64 _, [%0], %1;"
                     :: "r"(mbar_a), "r"((uint32_t)TILE_B) : "memory");
        asm volatile(
            "cp.async.bulk.shared::cta.global.mbarrier::complete_tx::bytes "
            "[%0], [%1], %2, [%3];"
            :: "r"(smem_u32(tile)),
               "l"(cpt + (size_t)blockIdx.x * (NPB * C_CFG)),
               "r"((uint32_t)TILE_B), "r"(mbar_a)
            : "memory");
    }

    // Parent gather overlaps the TMA transfer.
    const int   pidx = parents[gwarp * 32 + lane];
    const float pp   = prev[pidx];
    float p[8];
#pragma unroll
    for (int j = 0; j < 8; j++)
        p[j] = __shfl_sync(0xffffffffu, pp, pbase | j);

    // Wait for the CPT tile (parity 0).
    {
        uint32_t done;
        asm volatile(
            "{\n\t.reg .pred q;\n\t"
            "mbarrier.try_wait.parity.shared.b64 q, [%1], 0;\n\t"
            "selp.b32 %0, 1, 0, q;\n\t}"
            : "=r"(done) : "r"(mbar_a) : "memory");
        while (!done) {
            asm volatile(
                "{\n\t.reg .pred q;\n\t"
                "mbarrier.try_wait.parity.shared.b64 q, [%1], 0, 1000000;\n\t"
                "selp.b32 %0, 1, 0, q;\n\t}"
                : "=r"(done) : "r"(mbar_a) : "memory");
        }
    }

    // LDS + tanh + folds (parents 7,6 inline; 2,1,0 across iterations).
    const float4* row = reinterpret_cast<const float4*>(tile + nlocal * C_CFG) + gl;
    float r_i[8];
#pragma unroll
    for (int i = 0; i < 8; i++) {
        float4 v = row[i * 8];                 // configs i*32 + gl*4 .. +3
        float s0 = fast_tanh(0.5f * v.x);
        float s1 = fast_tanh(0.5f * v.y);
        float s2 = fast_tanh(0.5f * v.z);
        float s3 = fast_tanh(0.5f * v.w);
        float t0 = fmaf(p[7], s1 - s0, s0);
        float t1 = fmaf(p[7], s3 - s2, s2);
        r_i[i]   = fmaf(p[6], t1 - t0, t0);
    }
    float q0 = fmaf(p[2], r_i[1] - r_i[0], r_i[0]);
    float q1 = fmaf(p[2], r_i[3] - r_i[2], r_i[2]);
    float q2 = fmaf(p[2], r_i[5] - r_i[4], r_i[4]);
    float q3 = fmaf(p[2], r_i[7] - r_i[6], r_i[6]);
    float h0 = fmaf(p[1], q1 - q0, q0);
    float h1 = fmaf(p[1], q3 - q2, q2);
    float r  = fmaf(p[0], h1 - h0, h0);

#pragma unroll
    for (int b = 0; b < 3; b++) {
        int   msk = 1 << b;
        float o   = __shfl_xor_sync(0xffffffffu, r, msk);
        float a0  = (lane & msk) ? o : r;
        float a1  = (lane & msk) ? r : o;
        r = fmaf(p[5 - b], a1 - a0, a0);
    }

    if (gl == 0)
        out[blockIdx.x * NPB + nlocal] = fmaf(0.5f, r, 0.5f);
}

extern "C" void kernel_launch(void* const* d_in, const int* in_sizes, int n_in,
                              void* d_out, int out_size) {
    const float* root    = (const float*)d_in[0];  // [M]
    const float* cpt     = (const float*)d_in[1];  // [L, M, C]
    const int*   parents = (const int*)  d_in[2];  // [L, M, K]
    float*       out     = (float*)d_out;          // [(L+1)*M]

    root_kernel<<<(M_NODES + 255) / 256, 256>>>(root, out);

    for (int l = 0; l < N_LAYERS; l++) {
        layer_kernel<<<M_NODES / NPB, TPB>>>(
            cpt     + (size_t)l * M_NODES * C_CFG,
            parents + (size_t)l * M_NODES * K_PAR,
            out     + (size_t)l * M_NODES,
            out     + (size_t)(l + 1) * M_NODES);
    }
}